// round 16
// baseline (speedup 1.0000x reference)
#include <cuda_runtime.h>
#include <cuda_fp16.h>
#include <cstdint>

#define NN 50000
#define DIN 256
#define NC 8
#define NE 1600000
#define TTB 64
#define TBK 782    // transform blocks (64 nodes each)
#define PB2 3125   // prep+step0 blocks (256 threads x 2 edges)
#define EB2 3125   // edge blocks (256 threads x 2 edges)
#define NB 196     // node blocks

// ---- static device scratch (allocation-free contract) ----
__device__ __align__(16) float g_logb0[NN * NC];
__device__ __align__(16) float g_agg[NN * NC];
__device__ __align__(16) __half g_Bh[NN * NC];    // fp16 beliefs
__device__ __align__(16) __half g_m0h[NN * NC];   // fp16 step-0 per-node message
__device__ __align__(16) __half g_Rn[NN * NC];    // fp16 step-0 reciprocal msg
__device__ __align__(16) __half g_RA[NE * NC];    // fp16 reciprocal messages (ping)
__device__ __align__(16) __half g_RB[NE * NC];    // fp16 reciprocal messages (pong)
__device__ __align__(16) int2 g_sd[NE];           // (src, dst)
__device__ __align__(16) int g_rv[NE];
__device__ __align__(16) int g_srv[NE];           // src[rv[e]]
__device__ int g_odd_nonzero;   // !=0 -> int32 indices; ==0 -> int64
__device__ int g_detect_done;   // sticky across replays (value deterministic)

__device__ __forceinline__ float frcp(float x) {
    float r;
    asm("rcp.approx.f32 %0, %1;" : "=f"(r) : "f"(x));
    return r;
}

// high-reuse node-table gather: keep in L1
__device__ __forceinline__ uint4 ldg_keep(const __half* p) {
    uint4 v;
    asm volatile("ld.global.nc.L1::evict_last.v4.u32 {%0,%1,%2,%3}, [%4];"
                 : "=r"(v.x), "=r"(v.y), "=r"(v.z), "=r"(v.w) : "l"(p));
    return v;
}

// single-use stream gather: don't pollute L1
__device__ __forceinline__ uint4 ldg_once(const __half* p) {
    uint4 v;
    asm volatile("ld.global.nc.L1::no_allocate.v4.u32 {%0,%1,%2,%3}, [%4];"
                 : "=r"(v.x), "=r"(v.y), "=r"(v.z), "=r"(v.w) : "l"(p));
    return v;
}

__device__ __forceinline__ int4 ldg_idx4(const void* p) {
    int4 v;
    asm volatile("ld.global.nc.L1::no_allocate.v4.s32 {%0,%1,%2,%3}, [%4];"
                 : "=r"(v.x), "=r"(v.y), "=r"(v.z), "=r"(v.w) : "l"(p));
    return v;
}

__device__ __forceinline__ int2 ldg_idx2(const void* p) {
    int2 v;
    asm volatile("ld.global.nc.L1::no_allocate.v2.s32 {%0,%1}, [%2];"
                 : "=r"(v.x), "=r"(v.y) : "l"(p));
    return v;
}

__device__ __forceinline__ void h8_to_f8(uint4 q, float* f) {
    const __half2* h = (const __half2*)&q;
#pragma unroll
    for (int c = 0; c < 4; c++) {
        float2 t = __half22float2(h[c]);
        f[2 * c] = t.x;
        f[2 * c + 1] = t.y;
    }
}

__device__ __forceinline__ int ld_acquire(const int* p) {
    int v;
    asm volatile("ld.global.acquire.gpu.b32 %0, [%1];" : "=r"(v) : "l"(p));
    return v;
}

__device__ __forceinline__ void pdl_sync() {
#if defined(__CUDA_ARCH__) && (__CUDA_ARCH__ >= 900)
    cudaGridDependencySynchronize();
#endif
}

#define CP_ASYNC_16(saddr, gptr) \
    asm volatile("cp.async.cg.shared.global [%0], [%1], 16;" :: "r"(saddr), "l"(gptr))
#define CP_COMMIT() asm volatile("cp.async.commit_group;")
#define CP_WAIT(n) asm volatile("cp.async.wait_group %0;" :: "n"(n))

// ---- K1: detect (block 0) + transform (blocks 1..TBK) ----
__global__ void __launch_bounds__(256) transform_kernel(
    const float* __restrict__ x, const float* __restrict__ W,
    const float* __restrict__ bias, const void* __restrict__ ei) {
    if (blockIdx.x == 0) {
        if (threadIdx.x == 0) g_odd_nonzero = 0;
        __syncthreads();
        const int* w = (const int*)ei;
        int v = 0;
#pragma unroll
        for (int j = 0; j < 16; j++) v |= w[2 * (threadIdx.x + j * 256) + 1];
        unsigned any = __ballot_sync(0xffffffffu, v != 0);
        if ((threadIdx.x & 31) == 0 && any) atomicOr(&g_odd_nonzero, 1);
        __syncthreads();
        __threadfence();
        if (threadIdx.x == 0)
            asm volatile("st.global.release.gpu.b32 [%0], %1;"
                         :: "l"(&g_detect_done), "r"(1) : "memory");
        return;
    }

    __shared__ __align__(16) float sx[2][TTB][36];
    __shared__ __align__(16) float sW[DIN * NC];
    __shared__ float sred[4][TTB][9];   // padded: conflict-free reduce
    __shared__ float sb[NC];

    int tid = threadIdx.x;
    int g = tid >> 6;       // k-group 0..3
    int ln = tid & 63;      // node-lane within block

    for (int i = tid; i < DIN * NC; i += 256) sW[i] = W[i];
    if (tid < NC) sb[tid] = bias[tid];

    int node0 = (blockIdx.x - 1) * TTB;

    unsigned int sx_base = (unsigned int)__cvta_generic_to_shared(&sx[0][0][0]);

#pragma unroll
    for (int i = 0; i < 2; i++) {
        int lin = i * 256 + tid;
        int row = lin >> 3, c4 = lin & 7;
        int nr = node0 + row;
        if (nr < NN) {
            unsigned int sa = sx_base + (unsigned int)((row * 36 + c4 * 4) * 4);
            CP_ASYNC_16(sa, x + (size_t)nr * DIN + c4 * 4);
        }
    }
    CP_COMMIT();

    float acc[NC] = {0.f, 0.f, 0.f, 0.f, 0.f, 0.f, 0.f, 0.f};
    int buf = 0;

#pragma unroll 1
    for (int chunk = 0; chunk < DIN / 32; chunk++) {
        if (chunk + 1 < DIN / 32) {
            int ob = buf ^ 1;
#pragma unroll
            for (int i = 0; i < 2; i++) {
                int lin = i * 256 + tid;
                int row = lin >> 3, c4 = lin & 7;
                int nr = node0 + row;
                if (nr < NN) {
                    unsigned int sa = sx_base +
                                      (unsigned int)(((ob * TTB + row) * 36 + c4 * 4) * 4);
                    CP_ASYNC_16(sa, x + (size_t)nr * DIN + (chunk + 1) * 32 + c4 * 4);
                }
            }
            CP_COMMIT();
            CP_WAIT(1);
        } else {
            CP_WAIT(0);
        }
        __syncthreads();

#pragma unroll
        for (int k4 = 0; k4 < 2; k4++) {
            float4 xv = *(const float4*)&sx[buf][ln][g * 8 + k4 * 4];
            int kg = chunk * 32 + g * 8 + k4 * 4;
            float xs[4] = {xv.x, xv.y, xv.z, xv.w};
#pragma unroll
            for (int j = 0; j < 4; j++) {
                float4 w0 = *(const float4*)&sW[(kg + j) * NC];
                float4 w1 = *(const float4*)&sW[(kg + j) * NC + 4];
                acc[0] = fmaf(xs[j], w0.x, acc[0]);
                acc[1] = fmaf(xs[j], w0.y, acc[1]);
                acc[2] = fmaf(xs[j], w0.z, acc[2]);
                acc[3] = fmaf(xs[j], w0.w, acc[3]);
                acc[4] = fmaf(xs[j], w1.x, acc[4]);
                acc[5] = fmaf(xs[j], w1.y, acc[5]);
                acc[6] = fmaf(xs[j], w1.z, acc[6]);
                acc[7] = fmaf(xs[j], w1.w, acc[7]);
            }
        }
        __syncthreads();
        buf ^= 1;
    }

    // cross-group reduce
#pragma unroll
    for (int c = 0; c < NC; c++) sred[g][ln][c] = acc[c];
    __syncthreads();

    if (tid >= TTB) return;
    int n = node0 + tid;
    if (n >= NN) return;

#pragma unroll
    for (int c = 0; c < NC; c++)
        acc[c] = ((sred[0][tid][c] + sred[1][tid][c]) +
                  (sred[2][tid][c] + sred[3][tid][c]));

    float m = -3.4e38f;
#pragma unroll
    for (int c = 0; c < NC; c++) {
        acc[c] += sb[c];
        m = fmaxf(m, acc[c]);
    }
    float e[NC], S = 0.f;
#pragma unroll
    for (int c = 0; c < NC; c++) {
        e[c] = __expf(acc[c] - m);
        S += e[c];
    }
    float lS = __logf(S);
    float iS = frcp(S);

    const float beta = 19.085536923187668f;  // e^3 - 1

    float lb[NC], B[NC], m0[NC], Rn[NC];
#pragma unroll
    for (int c = 0; c < NC; c++) {
        lb[c] = acc[c] - m - lS;
        B[c] = e[c] * iS;
        float qp = fmaf(beta, B[c], 1.0f);
        m0[c] = __logf(qp);   // per-edge const normalizer cancels per node
        Rn[c] = frcp(qp);
    }

    *(float4*)(g_logb0 + n * NC) = make_float4(lb[0], lb[1], lb[2], lb[3]);
    *(float4*)(g_logb0 + n * NC + 4) = make_float4(lb[4], lb[5], lb[6], lb[7]);
    *(float4*)(g_agg + n * NC) = make_float4(lb[0], lb[1], lb[2], lb[3]);
    *(float4*)(g_agg + n * NC + 4) = make_float4(lb[4], lb[5], lb[6], lb[7]);

    uint4 bq, mq, rq;
    __half2* bh = (__half2*)&bq;
    __half2* mh = (__half2*)&mq;
    __half2* rh = (__half2*)&rq;
#pragma unroll
    for (int c = 0; c < 4; c++) {
        bh[c] = __floats2half2_rn(B[2 * c], B[2 * c + 1]);
        mh[c] = __floats2half2_rn(m0[2 * c], m0[2 * c + 1]);
        rh[c] = __floats2half2_rn(Rn[2 * c], Rn[2 * c + 1]);
    }
    *(uint4*)(g_Bh + n * NC) = bq;
    *(uint4*)(g_m0h + n * NC) = mq;
    *(uint4*)(g_Rn + n * NC) = rq;
}

// ---- K2: prep + step0 fused (2 edges/thread) ----
__global__ void __launch_bounds__(256) prep_step0_kernel(const void* __restrict__ ei,
                                                         const void* __restrict__ rv) {
    int t = blockIdx.x * 256 + threadIdx.x;
    int e0 = t * 2;

    if (threadIdx.x == 0) {
        while (ld_acquire(&g_detect_done) == 0) __nanosleep(32);
    }
    __syncthreads();

    int s0, d0, r0, sv0, s1, d1, r1, sv1;
    if (g_odd_nonzero) {  // int32 inputs
        const int* e32 = (const int*)ei;
        const int* r32 = (const int*)rv;
        int2 ss = *(const int2*)(e32 + e0);
        int2 dd = *(const int2*)(e32 + NE + e0);
        int2 rr = *(const int2*)(r32 + e0);
        s0 = ss.x; s1 = ss.y; d0 = dd.x; d1 = dd.y; r0 = rr.x; r1 = rr.y;
        sv0 = e32[r0]; sv1 = e32[r1];
    } else {  // int64 inputs
        const long long* e64 = (const long long*)ei;
        const long long* r64 = (const long long*)rv;
        longlong2 ss = *(const longlong2*)(e64 + e0);
        longlong2 dd = *(const longlong2*)(e64 + NE + e0);
        longlong2 rr = *(const longlong2*)(r64 + e0);
        s0 = (int)ss.x; s1 = (int)ss.y; d0 = (int)dd.x; d1 = (int)dd.y;
        r0 = (int)rr.x; r1 = (int)rr.y;
        sv0 = (int)e64[r0]; sv1 = (int)e64[r1];
    }
    *(int4*)(g_sd + e0) = make_int4(s0, d0, s1, d1);
    *(int2*)(g_rv + e0) = make_int2(r0, r1);
    *(int2*)(g_srv + e0) = make_int2(sv0, sv1);

    pdl_sync();  // wait for transform (m0h, agg init)

    uint4 q0 = ldg_keep(g_m0h + s0 * NC);
    uint4 q1 = ldg_keep(g_m0h + s1 * NC);
    float a[NC], b[NC];
    h8_to_f8(q0, a);
    h8_to_f8(q1, b);

    float* p0 = g_agg + d0 * NC;
    float* p1 = g_agg + d1 * NC;
    asm volatile("red.global.add.v4.f32 [%0], {%1,%2,%3,%4};"
                 :: "l"(p0), "f"(a[0]), "f"(a[1]), "f"(a[2]), "f"(a[3]) : "memory");
    asm volatile("red.global.add.v4.f32 [%0], {%1,%2,%3,%4};"
                 :: "l"(p0 + 4), "f"(a[4]), "f"(a[5]), "f"(a[6]), "f"(a[7]) : "memory");
    asm volatile("red.global.add.v4.f32 [%0], {%1,%2,%3,%4};"
                 :: "l"(p1), "f"(b[0]), "f"(b[1]), "f"(b[2]), "f"(b[3]) : "memory");
    asm volatile("red.global.add.v4.f32 [%0], {%1,%2,%3,%4};"
                 :: "l"(p1 + 4), "f"(b[4]), "f"(b[5]), "f"(b[6]), "f"(b[7]) : "memory");
}

// per-edge message compute: low register pressure variant.
template <int OUT>
__device__ __forceinline__ void process_edge(uint4 bq, uint4 rq, int d,
                                             __half* Rnext, int ew) {
    const float beta = 19.085536923187668f;  // e^3 - 1

    float bf[NC], rf[NC], u[NC];
    h8_to_f8(bq, bf);
    h8_to_f8(rq, rf);
#pragma unroll
    for (int c = 0; c < NC; c++) u[c] = bf[c] * rf[c];

    float U = ((u[0] + u[1]) + (u[2] + u[3])) + ((u[4] + u[5]) + (u[6] + u[7]));
    float bi = beta * frcp(U);

    float* ap = g_agg + d * NC;

    {
        float lg[4];
#pragma unroll
        for (int c = 0; c < 4; c++)
            lg[c] = __logf(fmaf(bi, u[c], 1.0f));
        asm volatile("red.global.add.v4.f32 [%0], {%1,%2,%3,%4};"
                     :: "l"(ap), "f"(lg[0]), "f"(lg[1]), "f"(lg[2]), "f"(lg[3]) : "memory");
    }
    {
        float lg[4];
#pragma unroll
        for (int c = 4; c < 8; c++)
            lg[c - 4] = __logf(fmaf(bi, u[c], 1.0f));
        asm volatile("red.global.add.v4.f32 [%0], {%1,%2,%3,%4};"
                     :: "l"(ap + 4), "f"(lg[0]), "f"(lg[1]), "f"(lg[2]), "f"(lg[3]) : "memory");
    }

    if (OUT != 0) {
        uint4 o;
        __half2* oh = (__half2*)&o;
#pragma unroll
        for (int c = 0; c < 4; c++) {
            float q0 = fmaf(bi, u[2 * c], 1.0f);
            float q1 = fmaf(bi, u[2 * c + 1], 1.0f);
            oh[c] = __floats2half2_rn(frcp(q0), frcp(q1));
        }
        *(uint4*)(Rnext + (size_t)ew * NC) = o;
    }
}

// edge steps 1..4, 2 edges/thread, sequential per-edge compute.
// TBL: 0 = g_Rn via srv; 1 = g_RA via rv; 2 = g_RB via rv.
// OUT: 0 none (last step); 1 write g_RA; 2 write g_RB.
template <int TBL, int OUT>
__global__ void __launch_bounds__(256, 7) edge_step_kernel() {
    int t = blockIdx.x * 256 + threadIdx.x;
    int e0 = t * 2;

    // ---- pre-sync prefetch (data >=2 kernels old) ----
    int4 sd2 = ldg_idx4(g_sd + e0);
    int2 ii = (TBL == 0) ? ldg_idx2(g_srv + e0) : ldg_idx2(g_rv + e0);

    const __half* __restrict__ tbl =
        (TBL == 0) ? g_Rn : (TBL == 1 ? g_RA : g_RB);

    uint4 rq0, rq1;
    if (TBL == 0) {  // Rn: node table, high reuse -> keep in L1
        rq0 = ldg_keep(tbl + (size_t)ii.x * NC);
        rq1 = ldg_keep(tbl + (size_t)ii.y * NC);
    }

    pdl_sync();

    if (TBL != 0) {  // RA/RB: single-use stream -> don't pollute L1
        rq0 = ldg_once(tbl + (size_t)ii.x * NC);
        rq1 = ldg_once(tbl + (size_t)ii.y * NC);
    }
    uint4 bq0 = ldg_keep(g_Bh + sd2.x * NC);
    uint4 bq1 = ldg_keep(g_Bh + sd2.z * NC);

    __half* __restrict__ Rnext = (OUT == 1) ? g_RA : g_RB;

    process_edge<OUT>(bq0, rq0, sd2.y, Rnext, e0);
    process_edge<OUT>(bq1, rq1, sd2.w, Rnext, e0 + 1);
}

// Node update: log_b = normalize(agg). Non-last: Bh = exp(log_b), agg = log_b0.
template <bool LAST>
__global__ void __launch_bounds__(256) node_kernel(float* __restrict__ out) {
    int n = blockIdx.x * 256 + threadIdx.x;

    float4 l0, l1;
    if (!LAST && n < NN) {
        l0 = *(const float4*)(g_logb0 + n * NC);
        l1 = *(const float4*)(g_logb0 + n * NC + 4);
    }

    pdl_sync();
    if (n >= NN) return;

    float4 a0 = *(const float4*)(g_agg + n * NC);
    float4 a1 = *(const float4*)(g_agg + n * NC + 4);
    float v[NC] = {a0.x, a0.y, a0.z, a0.w, a1.x, a1.y, a1.z, a1.w};

    float m = v[0];
#pragma unroll
    for (int c = 1; c < NC; c++) m = fmaxf(m, v[c]);
    float e[NC], S = 0.f;
#pragma unroll
    for (int c = 0; c < NC; c++) {
        e[c] = __expf(v[c] - m);
        S += e[c];
    }

    if (LAST) {
        float lS = __logf(S) + m;
        *(float4*)(out + n * NC) =
            make_float4(v[0] - lS, v[1] - lS, v[2] - lS, v[3] - lS);
        *(float4*)(out + n * NC + 4) =
            make_float4(v[4] - lS, v[5] - lS, v[6] - lS, v[7] - lS);
    } else {
        float iS = frcp(S);
        uint4 bq;
        __half2* bh = (__half2*)&bq;
#pragma unroll
        for (int c = 0; c < 4; c++)
            bh[c] = __floats2half2_rn(e[2 * c] * iS, e[2 * c + 1] * iS);
        *(uint4*)(g_Bh + n * NC) = bq;
        *(float4*)(g_agg + n * NC) = l0;
        *(float4*)(g_agg + n * NC + 4) = l1;
    }
}

// host-side PDL launch helper (graph-capture legal)
static void launch_pdl(const void* func, int grid, int block, void** args) {
    cudaLaunchConfig_t cfg = {};
    cfg.gridDim = dim3(grid, 1, 1);
    cfg.blockDim = dim3(block, 1, 1);
    cfg.dynamicSmemBytes = 0;
    cfg.stream = 0;
    cudaLaunchAttribute attr[1];
    attr[0].id = cudaLaunchAttributeProgrammaticStreamSerialization;
    attr[0].val.programmaticStreamSerializationAllowed = 1;
    cfg.attrs = attr;
    cfg.numAttrs = 1;
    cudaLaunchKernelExC(&cfg, func, args);
}

extern "C" void kernel_launch(void* const* d_in, const int* in_sizes, int n_in,
                              void* d_out, int out_size) {
    const float* x = (const float*)d_in[0];
    const float* W = (const float*)d_in[1];
    const float* bias = (const float*)d_in[2];
    const void* ei = d_in[3];
    const void* rv = d_in[4];
    float* out = (float*)d_out;
    float* nullp = nullptr;

    transform_kernel<<<1 + TBK, 256>>>(x, W, bias, ei);

    void* k2_args[2] = {(void*)&ei, (void*)&rv};
    void* no_args[1] = {nullptr};
    void* node_args[1] = {&nullp};
    void* final_args[1] = {&out};

    launch_pdl((const void*)prep_step0_kernel, PB2, 256, k2_args);
    launch_pdl((const void*)node_kernel<false>, NB, 256, node_args);
    launch_pdl((const void*)edge_step_kernel<0, 1>, EB2, 256, no_args);  // s1: Rn[srv]->RA
    launch_pdl((const void*)node_kernel<false>, NB, 256, node_args);
    launch_pdl((const void*)edge_step_kernel<1, 2>, EB2, 256, no_args);  // s2: RA[rv]->RB
    launch_pdl((const void*)node_kernel<false>, NB, 256, node_args);
    launch_pdl((const void*)edge_step_kernel<2, 1>, EB2, 256, no_args);  // s3: RB[rv]->RA
    launch_pdl((const void*)node_kernel<false>, NB, 256, node_args);
    launch_pdl((const void*)edge_step_kernel<1, 0>, EB2, 256, no_args);  // s4: RA[rv]
    launch_pdl((const void*)node_kernel<true>, NB, 256, final_args);
}

// round 17
// speedup vs baseline: 1.0291x; 1.0291x over previous
#include <cuda_runtime.h>
#include <cuda_fp16.h>
#include <cstdint>

#define NN 50000
#define DIN 256
#define NC 8
#define NE 1600000
#define TTB 64
#define TBK 782    // transform blocks (64 nodes each)
#define PB2 3125   // prep+step0 blocks (256 threads x 2 edges)
#define EB2 3125   // edge blocks (256 threads x 2 edges)
#define NB 196     // node blocks

// ---- static device scratch (allocation-free contract) ----
__device__ __align__(16) float g_logb0[NN * NC];
__device__ __align__(16) float g_agg[NN * NC];
__device__ __align__(16) __half g_Bh[NN * NC];    // fp16 beliefs
__device__ __align__(16) __half g_m0h[NN * NC];   // fp16 step-0 per-node message
__device__ __align__(16) __half g_Rn[NN * NC];    // fp16 step-0 reciprocal msg
__device__ __align__(16) __half g_RA[NE * NC];    // fp16 reciprocal messages (ping)
__device__ __align__(16) __half g_RB[NE * NC];    // fp16 reciprocal messages (pong)
__device__ __align__(16) int2 g_sd[NE];           // (src, dst)
__device__ __align__(16) int g_rv[NE];
__device__ __align__(16) int g_srv[NE];           // src[rv[e]]
__device__ int g_odd_nonzero;   // !=0 -> int32 indices; ==0 -> int64
__device__ int g_detect_done;   // sticky across replays (value deterministic)

__device__ __forceinline__ float frcp(float x) {
    float r;
    asm("rcp.approx.f32 %0, %1;" : "=f"(r) : "f"(x));
    return r;
}

__device__ __forceinline__ void h8_to_f8(uint4 q, float* f) {
    const __half2* h = (const __half2*)&q;
#pragma unroll
    for (int c = 0; c < 4; c++) {
        float2 t = __half22float2(h[c]);
        f[2 * c] = t.x;
        f[2 * c + 1] = t.y;
    }
}

__device__ __forceinline__ int ld_acquire(const int* p) {
    int v;
    asm volatile("ld.global.acquire.gpu.b32 %0, [%1];" : "=r"(v) : "l"(p));
    return v;
}

__device__ __forceinline__ void pdl_sync() {
#if defined(__CUDA_ARCH__) && (__CUDA_ARCH__ >= 900)
    cudaGridDependencySynchronize();
#endif
}

#define CP_ASYNC_16(saddr, gptr) \
    asm volatile("cp.async.cg.shared.global [%0], [%1], 16;" :: "r"(saddr), "l"(gptr))
#define CP_COMMIT() asm volatile("cp.async.commit_group;")
#define CP_WAIT(n) asm volatile("cp.async.wait_group %0;" :: "n"(n))

// ---- K1: detect (block 0) + transform (blocks 1..TBK) ----
__global__ void __launch_bounds__(256) transform_kernel(
    const float* __restrict__ x, const float* __restrict__ W,
    const float* __restrict__ bias, const void* __restrict__ ei) {
    if (blockIdx.x == 0) {
        if (threadIdx.x == 0) g_odd_nonzero = 0;
        __syncthreads();
        const int* w = (const int*)ei;
        int v = 0;
#pragma unroll
        for (int j = 0; j < 16; j++) v |= w[2 * (threadIdx.x + j * 256) + 1];
        unsigned any = __ballot_sync(0xffffffffu, v != 0);
        if ((threadIdx.x & 31) == 0 && any) atomicOr(&g_odd_nonzero, 1);
        __syncthreads();
        __threadfence();
        if (threadIdx.x == 0)
            asm volatile("st.global.release.gpu.b32 [%0], %1;"
                         :: "l"(&g_detect_done), "r"(1) : "memory");
        return;
    }

    __shared__ __align__(16) float sx[2][TTB][36];
    __shared__ __align__(16) float sW[DIN * NC];
    __shared__ float sred[4][TTB][9];   // padded: conflict-free reduce
    __shared__ float sb[NC];

    int tid = threadIdx.x;
    int g = tid >> 6;       // k-group 0..3
    int ln = tid & 63;      // node-lane within block

    for (int i = tid; i < DIN * NC; i += 256) sW[i] = W[i];
    if (tid < NC) sb[tid] = bias[tid];

    int node0 = (blockIdx.x - 1) * TTB;

    unsigned int sx_base = (unsigned int)__cvta_generic_to_shared(&sx[0][0][0]);

#pragma unroll
    for (int i = 0; i < 2; i++) {
        int lin = i * 256 + tid;
        int row = lin >> 3, c4 = lin & 7;
        int nr = node0 + row;
        if (nr < NN) {
            unsigned int sa = sx_base + (unsigned int)((row * 36 + c4 * 4) * 4);
            CP_ASYNC_16(sa, x + (size_t)nr * DIN + c4 * 4);
        }
    }
    CP_COMMIT();

    float acc[NC] = {0.f, 0.f, 0.f, 0.f, 0.f, 0.f, 0.f, 0.f};
    int buf = 0;

#pragma unroll 1
    for (int chunk = 0; chunk < DIN / 32; chunk++) {
        if (chunk + 1 < DIN / 32) {
            int ob = buf ^ 1;
#pragma unroll
            for (int i = 0; i < 2; i++) {
                int lin = i * 256 + tid;
                int row = lin >> 3, c4 = lin & 7;
                int nr = node0 + row;
                if (nr < NN) {
                    unsigned int sa = sx_base +
                                      (unsigned int)(((ob * TTB + row) * 36 + c4 * 4) * 4);
                    CP_ASYNC_16(sa, x + (size_t)nr * DIN + (chunk + 1) * 32 + c4 * 4);
                }
            }
            CP_COMMIT();
            CP_WAIT(1);
        } else {
            CP_WAIT(0);
        }
        __syncthreads();

#pragma unroll
        for (int k4 = 0; k4 < 2; k4++) {
            float4 xv = *(const float4*)&sx[buf][ln][g * 8 + k4 * 4];
            int kg = chunk * 32 + g * 8 + k4 * 4;
            float xs[4] = {xv.x, xv.y, xv.z, xv.w};
#pragma unroll
            for (int j = 0; j < 4; j++) {
                float4 w0 = *(const float4*)&sW[(kg + j) * NC];
                float4 w1 = *(const float4*)&sW[(kg + j) * NC + 4];
                acc[0] = fmaf(xs[j], w0.x, acc[0]);
                acc[1] = fmaf(xs[j], w0.y, acc[1]);
                acc[2] = fmaf(xs[j], w0.z, acc[2]);
                acc[3] = fmaf(xs[j], w0.w, acc[3]);
                acc[4] = fmaf(xs[j], w1.x, acc[4]);
                acc[5] = fmaf(xs[j], w1.y, acc[5]);
                acc[6] = fmaf(xs[j], w1.z, acc[6]);
                acc[7] = fmaf(xs[j], w1.w, acc[7]);
            }
        }
        __syncthreads();
        buf ^= 1;
    }

    // cross-group reduce
#pragma unroll
    for (int c = 0; c < NC; c++) sred[g][ln][c] = acc[c];
    __syncthreads();

    if (tid >= TTB) return;
    int n = node0 + tid;
    if (n >= NN) return;

#pragma unroll
    for (int c = 0; c < NC; c++)
        acc[c] = ((sred[0][tid][c] + sred[1][tid][c]) +
                  (sred[2][tid][c] + sred[3][tid][c]));

    float m = -3.4e38f;
#pragma unroll
    for (int c = 0; c < NC; c++) {
        acc[c] += sb[c];
        m = fmaxf(m, acc[c]);
    }
    float e[NC], S = 0.f;
#pragma unroll
    for (int c = 0; c < NC; c++) {
        e[c] = __expf(acc[c] - m);
        S += e[c];
    }
    float lS = __logf(S);
    float iS = frcp(S);

    const float beta = 19.085536923187668f;  // e^3 - 1

    float lb[NC], B[NC], m0[NC], Rn[NC];
#pragma unroll
    for (int c = 0; c < NC; c++) {
        lb[c] = acc[c] - m - lS;
        B[c] = e[c] * iS;
        float qp = fmaf(beta, B[c], 1.0f);
        m0[c] = __logf(qp);   // per-edge const normalizer cancels per node
        Rn[c] = frcp(qp);
    }

    *(float4*)(g_logb0 + n * NC) = make_float4(lb[0], lb[1], lb[2], lb[3]);
    *(float4*)(g_logb0 + n * NC + 4) = make_float4(lb[4], lb[5], lb[6], lb[7]);
    *(float4*)(g_agg + n * NC) = make_float4(lb[0], lb[1], lb[2], lb[3]);
    *(float4*)(g_agg + n * NC + 4) = make_float4(lb[4], lb[5], lb[6], lb[7]);

    uint4 bq, mq, rq;
    __half2* bh = (__half2*)&bq;
    __half2* mh = (__half2*)&mq;
    __half2* rh = (__half2*)&rq;
#pragma unroll
    for (int c = 0; c < 4; c++) {
        bh[c] = __floats2half2_rn(B[2 * c], B[2 * c + 1]);
        mh[c] = __floats2half2_rn(m0[2 * c], m0[2 * c + 1]);
        rh[c] = __floats2half2_rn(Rn[2 * c], Rn[2 * c + 1]);
    }
    *(uint4*)(g_Bh + n * NC) = bq;
    *(uint4*)(g_m0h + n * NC) = mq;
    *(uint4*)(g_Rn + n * NC) = rq;
}

// ---- K2: prep + step0 fused (2 edges/thread) ----
__global__ void __launch_bounds__(256) prep_step0_kernel(const void* __restrict__ ei,
                                                         const void* __restrict__ rv) {
    int t = blockIdx.x * 256 + threadIdx.x;
    int e0 = t * 2;

    if (threadIdx.x == 0) {
        while (ld_acquire(&g_detect_done) == 0) __nanosleep(32);
    }
    __syncthreads();

    int s0, d0, r0, sv0, s1, d1, r1, sv1;
    if (g_odd_nonzero) {  // int32 inputs
        const int* e32 = (const int*)ei;
        const int* r32 = (const int*)rv;
        int2 ss = *(const int2*)(e32 + e0);
        int2 dd = *(const int2*)(e32 + NE + e0);
        int2 rr = *(const int2*)(r32 + e0);
        s0 = ss.x; s1 = ss.y; d0 = dd.x; d1 = dd.y; r0 = rr.x; r1 = rr.y;
        sv0 = e32[r0]; sv1 = e32[r1];
    } else {  // int64 inputs
        const long long* e64 = (const long long*)ei;
        const long long* r64 = (const long long*)rv;
        longlong2 ss = *(const longlong2*)(e64 + e0);
        longlong2 dd = *(const longlong2*)(e64 + NE + e0);
        longlong2 rr = *(const longlong2*)(r64 + e0);
        s0 = (int)ss.x; s1 = (int)ss.y; d0 = (int)dd.x; d1 = (int)dd.y;
        r0 = (int)rr.x; r1 = (int)rr.y;
        sv0 = (int)e64[r0]; sv1 = (int)e64[r1];
    }
    *(int4*)(g_sd + e0) = make_int4(s0, d0, s1, d1);
    *(int2*)(g_rv + e0) = make_int2(r0, r1);
    *(int2*)(g_srv + e0) = make_int2(sv0, sv1);

    pdl_sync();  // wait for transform (m0h, agg init)

    uint4 q0 = *(const uint4*)(g_m0h + s0 * NC);
    uint4 q1 = *(const uint4*)(g_m0h + s1 * NC);
    float a[NC], b[NC];
    h8_to_f8(q0, a);
    h8_to_f8(q1, b);

    float* p0 = g_agg + d0 * NC;
    float* p1 = g_agg + d1 * NC;
    asm volatile("red.global.add.v4.f32 [%0], {%1,%2,%3,%4};"
                 :: "l"(p0), "f"(a[0]), "f"(a[1]), "f"(a[2]), "f"(a[3]) : "memory");
    asm volatile("red.global.add.v4.f32 [%0], {%1,%2,%3,%4};"
                 :: "l"(p0 + 4), "f"(a[4]), "f"(a[5]), "f"(a[6]), "f"(a[7]) : "memory");
    asm volatile("red.global.add.v4.f32 [%0], {%1,%2,%3,%4};"
                 :: "l"(p1), "f"(b[0]), "f"(b[1]), "f"(b[2]), "f"(b[3]) : "memory");
    asm volatile("red.global.add.v4.f32 [%0], {%1,%2,%3,%4};"
                 :: "l"(p1 + 4), "f"(b[4]), "f"(b[5]), "f"(b[6]), "f"(b[7]) : "memory");
}

// per-edge message compute: low register pressure variant.
template <int OUT>
__device__ __forceinline__ void process_edge(uint4 bq, uint4 rq, int d,
                                             __half* Rnext, int ew) {
    const float beta = 19.085536923187668f;  // e^3 - 1

    float bf[NC], rf[NC], u[NC];
    h8_to_f8(bq, bf);
    h8_to_f8(rq, rf);
#pragma unroll
    for (int c = 0; c < NC; c++) u[c] = bf[c] * rf[c];

    float U = ((u[0] + u[1]) + (u[2] + u[3])) + ((u[4] + u[5]) + (u[6] + u[7]));
    float bi = beta * frcp(U);

    float* ap = g_agg + d * NC;

    {
        float lg[4];
#pragma unroll
        for (int c = 0; c < 4; c++)
            lg[c] = __logf(fmaf(bi, u[c], 1.0f));
        asm volatile("red.global.add.v4.f32 [%0], {%1,%2,%3,%4};"
                     :: "l"(ap), "f"(lg[0]), "f"(lg[1]), "f"(lg[2]), "f"(lg[3]) : "memory");
    }
    {
        float lg[4];
#pragma unroll
        for (int c = 4; c < 8; c++)
            lg[c - 4] = __logf(fmaf(bi, u[c], 1.0f));
        asm volatile("red.global.add.v4.f32 [%0], {%1,%2,%3,%4};"
                     :: "l"(ap + 4), "f"(lg[0]), "f"(lg[1]), "f"(lg[2]), "f"(lg[3]) : "memory");
    }

    if (OUT != 0) {
        uint4 o;
        __half2* oh = (__half2*)&o;
#pragma unroll
        for (int c = 0; c < 4; c++) {
            float q0 = fmaf(bi, u[2 * c], 1.0f);
            float q1 = fmaf(bi, u[2 * c + 1], 1.0f);
            oh[c] = __floats2half2_rn(frcp(q0), frcp(q1));
        }
        *(uint4*)(Rnext + (size_t)ew * NC) = o;
    }
}

// edge steps 1..4, 2 edges/thread, sequential per-edge compute.
// TBL: 0 = g_Rn via srv; 1 = g_RA via rv; 2 = g_RB via rv.
// OUT: 0 none (last step); 1 write g_RA; 2 write g_RB.
template <int TBL, int OUT>
__global__ void __launch_bounds__(256, 8) edge_step_kernel() {
    int t = blockIdx.x * 256 + threadIdx.x;
    int e0 = t * 2;

    // ---- pre-sync prefetch (data >=2 kernels old) ----
    int4 sd2 = *(const int4*)(g_sd + e0);
    int2 ii = (TBL == 0) ? *(const int2*)(g_srv + e0) : *(const int2*)(g_rv + e0);

    const __half* __restrict__ tbl =
        (TBL == 0) ? g_Rn : (TBL == 1 ? g_RA : g_RB);

    uint4 rq0, rq1;
    if (TBL == 0) {  // Rn written by K1: safe pre-sync
        rq0 = *(const uint4*)(tbl + (size_t)ii.x * NC);
        rq1 = *(const uint4*)(tbl + (size_t)ii.y * NC);
    }

    pdl_sync();

    if (TBL != 0) {  // RA/RB written by the prior edge step: post-sync only
        rq0 = *(const uint4*)(tbl + (size_t)ii.x * NC);
        rq1 = *(const uint4*)(tbl + (size_t)ii.y * NC);
    }
    uint4 bq0 = *(const uint4*)(g_Bh + sd2.x * NC);
    uint4 bq1 = *(const uint4*)(g_Bh + sd2.z * NC);

    __half* __restrict__ Rnext = (OUT == 1) ? g_RA : g_RB;

    process_edge<OUT>(bq0, rq0, sd2.y, Rnext, e0);
    process_edge<OUT>(bq1, rq1, sd2.w, Rnext, e0 + 1);
}

// Node update: log_b = normalize(agg). Non-last: Bh = exp(log_b), agg = log_b0.
template <bool LAST>
__global__ void __launch_bounds__(256) node_kernel(float* __restrict__ out) {
    int n = blockIdx.x * 256 + threadIdx.x;

    float4 l0, l1;
    if (!LAST && n < NN) {
        l0 = *(const float4*)(g_logb0 + n * NC);
        l1 = *(const float4*)(g_logb0 + n * NC + 4);
    }

    pdl_sync();
    if (n >= NN) return;

    float4 a0 = *(const float4*)(g_agg + n * NC);
    float4 a1 = *(const float4*)(g_agg + n * NC + 4);
    float v[NC] = {a0.x, a0.y, a0.z, a0.w, a1.x, a1.y, a1.z, a1.w};

    float m = v[0];
#pragma unroll
    for (int c = 1; c < NC; c++) m = fmaxf(m, v[c]);
    float e[NC], S = 0.f;
#pragma unroll
    for (int c = 0; c < NC; c++) {
        e[c] = __expf(v[c] - m);
        S += e[c];
    }

    if (LAST) {
        float lS = __logf(S) + m;
        *(float4*)(out + n * NC) =
            make_float4(v[0] - lS, v[1] - lS, v[2] - lS, v[3] - lS);
        *(float4*)(out + n * NC + 4) =
            make_float4(v[4] - lS, v[5] - lS, v[6] - lS, v[7] - lS);
    } else {
        float iS = frcp(S);
        uint4 bq;
        __half2* bh = (__half2*)&bq;
#pragma unroll
        for (int c = 0; c < 4; c++)
            bh[c] = __floats2half2_rn(e[2 * c] * iS, e[2 * c + 1] * iS);
        *(uint4*)(g_Bh + n * NC) = bq;
        *(float4*)(g_agg + n * NC) = l0;
        *(float4*)(g_agg + n * NC + 4) = l1;
    }
}

// host-side PDL launch helper (graph-capture legal)
static void launch_pdl(const void* func, int grid, int block, void** args) {
    cudaLaunchConfig_t cfg = {};
    cfg.gridDim = dim3(grid, 1, 1);
    cfg.blockDim = dim3(block, 1, 1);
    cfg.dynamicSmemBytes = 0;
    cfg.stream = 0;
    cudaLaunchAttribute attr[1];
    attr[0].id = cudaLaunchAttributeProgrammaticStreamSerialization;
    attr[0].val.programmaticStreamSerializationAllowed = 1;
    cfg.attrs = attr;
    cfg.numAttrs = 1;
    cudaLaunchKernelExC(&cfg, func, args);
}

extern "C" void kernel_launch(void* const* d_in, const int* in_sizes, int n_in,
                              void* d_out, int out_size) {
    const float* x = (const float*)d_in[0];
    const float* W = (const float*)d_in[1];
    const float* bias = (const float*)d_in[2];
    const void* ei = d_in[3];
    const void* rv = d_in[4];
    float* out = (float*)d_out;
    float* nullp = nullptr;

    transform_kernel<<<1 + TBK, 256>>>(x, W, bias, ei);

    void* k2_args[2] = {(void*)&ei, (void*)&rv};
    void* no_args[1] = {nullptr};
    void* node_args[1] = {&nullp};
    void* final_args[1] = {&out};

    launch_pdl((const void*)prep_step0_kernel, PB2, 256, k2_args);
    launch_pdl((const void*)node_kernel<false>, NB, 256, node_args);
    launch_pdl((const void*)edge_step_kernel<0, 1>, EB2, 256, no_args);  // s1: Rn[srv]->RA
    launch_pdl((const void*)node_kernel<false>, NB, 256, node_args);
    launch_pdl((const void*)edge_step_kernel<1, 2>, EB2, 256, no_args);  // s2: RA[rv]->RB
    launch_pdl((const void*)node_kernel<false>, NB, 256, node_args);
    launch_pdl((const void*)edge_step_kernel<2, 1>, EB2, 256, no_args);  // s3: RB[rv]->RA
    launch_pdl((const void*)node_kernel<false>, NB, 256, node_args);
    launch_pdl((const void*)edge_step_kernel<1, 0>, EB2, 256, no_args);  // s4: RA[rv]
    launch_pdl((const void*)node_kernel<true>, NB, 256, final_args);
}